// round 15
// baseline (speedup 1.0000x reference)
#include <cuda_runtime.h>
#include <cuda_fp16.h>
#include <math.h>
#include <stdint.h>

#define DIM  1024
#define NEXP 8
#define NTOK 16384
#define BM   128
#define BN   128
#define BK   64
#define KIT  (DIM/BK)        // 16 stages
#define ROWB 144             // 64 halves (128B) + 16B pad
#define OFF_AH 0
#define OFF_BH (128*ROWB)               // 18432
#define STGB   (OFF_BH + 128*ROWB)      // 36864
#define NSTG 3
#define SMEM_BYTES (NSTG*STGB)          // 110592  (2 CTAs/SM)
#define GAP_THRESH 5.0e-3f
#define NROW (NTOK/BM)                  // 128 row-blocks
#define NTILE (DIM/BN)                  // 8 n-tiles per row-block

// ---------------- device-global scratch (allocation-free) ----------------
__device__ __half g_Xh[(size_t)NTOK * DIM];
__device__ __half g_Wh[(size_t)(1 + NEXP) * DIM * DIM];   // [N][K] fp16
__device__ float  g_part[(size_t)NTOK * 64];              // 8 tiles x 8 words
__device__ int    g_cnt[NEXP];
__device__ int    g_done[NROW];
__device__ int    g_tok[NEXP * NTOK];
__device__ float  g_p[NTOK];

// ---------------- PTX helpers ----------------
static __device__ __forceinline__ uint32_t smem_u32(const void* p) {
    uint32_t a;
    asm("{ .reg .u64 t; cvta.to.shared.u64 t, %1; cvt.u32.u64 %0, t; }" : "=r"(a) : "l"(p));
    return a;
}
#define CP_ASYNC16(dst, src, sz) \
    asm volatile("cp.async.cg.shared.global [%0], [%1], 16, %2;" \
                 :: "r"(dst), "l"(src), "r"(sz) : "memory")
#define CP_COMMIT() asm volatile("cp.async.commit_group;" ::: "memory")
#define CP_WAIT_1() asm volatile("cp.async.wait_group 1;" ::: "memory")

#define LDM_X4(r, addr) \
    asm volatile("ldmatrix.sync.aligned.m8n8.x4.shared.b16 {%0,%1,%2,%3}, [%4];" \
                 : "=r"((r)[0]), "=r"((r)[1]), "=r"((r)[2]), "=r"((r)[3]) : "r"(addr))

#define MMA(d, a, b0_, b1_) \
    asm volatile("mma.sync.aligned.m16n8k16.row.col.f32.f16.f16.f32 " \
                 "{%0,%1,%2,%3},{%4,%5,%6,%7},{%8,%9},{%0,%1,%2,%3};" \
                 : "+f"((d)[0]), "+f"((d)[1]), "+f"((d)[2]), "+f"((d)[3]) \
                 : "r"((a)[0]), "r"((a)[1]), "r"((a)[2]), "r"((a)[3]), \
                   "r"(b0_), "r"(b1_))

// ---- top-2 merge (first-index tie-break, jnp.argmax compatible) ----
static __device__ __forceinline__ void merge_top2(float& m1, int& i1, float& m2, int& i2,
                                                  float om1, int oi1, float om2, int oi2) {
    if (om1 > m1 || (om1 == m1 && oi1 < i1)) {
        float c = m1; int ci = i1;
        m1 = om1; i1 = oi1;
        if (om2 > c || (om2 == c && oi2 < ci)) { m2 = om2; i2 = oi2; }
        else                                   { m2 = c;   i2 = ci;  }
    } else {
        if (om1 > m2 || (om1 == m2 && oi1 < i2)) { m2 = om1; i2 = oi1; }
    }
}
static __device__ __forceinline__ void merge5(float& m1, int& i1, float& m2, int& i2, float& s,
                                              float om1, int oi1, float om2, int oi2, float os) {
    const float M = fmaxf(m1, om1);
    s = s * expf(m1 - M) + os * expf(om1 - M);
    merge_top2(m1, i1, m2, i2, om1, oi1, om2, oi2);
}

// =====================================================================
// Prep: blocks [0,1024) transpose Wg -> g_Wh[z=0]; blocks [1024, 17408)
// convert x -> g_Xh. Block 0 resets counters. 256 threads.
// =====================================================================
#define NBLK_WG 1024
#define NBLK_X  (NTOK * DIM / 4 / 256)   // 16384
__global__ __launch_bounds__(256) void k_prep(const float* __restrict__ X,
                                              const float* __restrict__ Wg) {
    const int id = blockIdx.x;
    const int tid = threadIdx.x;
    if (id == 0) {
        if (tid < NEXP) g_cnt[tid] = 0;
        if (tid < NROW) g_done[tid] = 0;
    }

    if (id < NBLK_WG) {
        __shared__ float t[32][33];
        const int bx = id & 31, by = id >> 5;
        const int tx = tid & 31, ty = tid >> 5;
        #pragma unroll
        for (int i = 0; i < 32; i += 8)
            t[ty + i][tx] = Wg[(size_t)(by * 32 + ty + i) * DIM + bx * 32 + tx];
        __syncthreads();
        #pragma unroll
        for (int i = 0; i < 32; i += 8)
            g_Wh[(size_t)(bx * 32 + ty + i) * DIM + by * 32 + tx] =
                __float2half_rn(t[tx][ty + i]);
    } else {
        const size_t i = (size_t)(id - NBLK_WG) * 256 + tid;
        float4 v = ((const float4*)X)[i];
        ((__half2*)g_Xh)[2 * i]     = __halves2half2(__float2half_rn(v.x), __float2half_rn(v.y));
        ((__half2*)g_Xh)[2 * i + 1] = __halves2half2(__float2half_rn(v.z), __float2half_rn(v.w));
    }
}

// =====================================================================
// fp16 GEMM via mma.sync (fp32 acc), 128x128 tile, BK=64, 3-stage pipeline.
// 256 threads = 8 warps as 4(m) x 2(n); warp tile 32x64. 2 CTAs/SM.
// MODE 0: gating; grid (8, 128+16): GEMM tiles + fused route + We transpose.
// MODE 1: expert -> out = relu(x@We[e] + be[e]) * p   (rows gathered)
// =====================================================================
template <int MODE>
__global__ __launch_bounds__(256, 2) void k_gemm(const float* __restrict__ bias_,
                                                 float* __restrict__ C,
                                                 const float* __restrict__ X32,
                                                 const float* __restrict__ Wg32,
                                                 const float* __restrict__ We32) {
    extern __shared__ char smem[];
    __shared__ int stok[BM];

    const int tid = threadIdx.x;
    const int lane = tid & 31;
    const int w = tid >> 5;

    // ================= We transpose CTAs (MODE 0, y >= 128) ================
    if (MODE == 0 && blockIdx.y >= NROW) {
        const int c_ = (blockIdx.y - NROW) * 8 + blockIdx.x;   // 0..127
        const int e = c_ >> 4;
        const int c0 = (c_ & 15) * 64;
        const float* src = We32 + (size_t)e * DIM * DIM;       // [K][N]
        __half* dst = g_Wh + (size_t)(1 + e) * DIM * DIM;      // [N][K]
        float* sbuf = (float*)smem;             // [64][65]
        for (int r0 = 0; r0 < DIM; r0 += 64) {
            float4 va[2][2];
            #pragma unroll
            for (int h = 0; h < 2; ++h) {
                const int vt = tid + 256 * h;
                const int rowt = vt >> 3, colt = (vt & 7) * 8;
                va[h][0] = *(const float4*)&src[(size_t)(r0 + rowt) * DIM + c0 + colt];
                va[h][1] = *(const float4*)&src[(size_t)(r0 + rowt) * DIM + c0 + colt + 4];
            }
            __syncthreads();
            #pragma unroll
            for (int h = 0; h < 2; ++h) {
                const int vt = tid + 256 * h;
                const int rowt = vt >> 3, colt = (vt & 7) * 8;
                float* dr = &sbuf[rowt * 65 + colt];
                dr[0] = va[h][0].x; dr[1] = va[h][0].y; dr[2] = va[h][0].z; dr[3] = va[h][0].w;
                dr[4] = va[h][1].x; dr[5] = va[h][1].y; dr[6] = va[h][1].z; dr[7] = va[h][1].w;
            }
            __syncthreads();
            #pragma unroll
            for (int h = 0; h < 2; ++h) {
                const int vt = tid + 256 * h;
                const int rowt = vt >> 3, colt = (vt & 7) * 8;
                __half tmp[8];
                #pragma unroll
                for (int j = 0; j < 8; ++j)
                    tmp[j] = __float2half_rn(sbuf[(colt + j) * 65 + rowt]);
                *(uint4*)&dst[(size_t)(c0 + rowt) * DIM + r0 + colt] = *(uint4*)tmp;
            }
            __syncthreads();
        }
        return;
    }

    const int mbase = blockIdx.y * BM;
    const int nbase = blockIdx.x * BN;

    const float* bias = bias_;
    size_t woff = 0;
    if (MODE == 1) {
        const int e = blockIdx.z;
        const int cnt = g_cnt[e];
        if (mbase >= cnt) return;
        woff = (size_t)(1 + e) * DIM * DIM;
        bias = bias_ + e * DIM;
        if (tid < BM) {
            const int i = mbase + tid;
            stok[tid] = (i < cnt) ? g_tok[e * NTOK + i] : -1;
        }
    } else {
        if (tid < BM) stok[tid] = mbase + tid;
    }
    __syncthreads();

    const uint32_t sb = smem_u32(smem);

    // ---- cp.async: one 128B row per thread (8 x 16B chunks)
    const char* gp;
    uint32_t sz = 16u, so;
    if (tid < 128) {
        const int tok = stok[tid];
        sz = (tok >= 0) ? 16u : 0u;
        gp = (const char*)(g_Xh + (size_t)(tok >= 0 ? tok : 0) * DIM);
        so = OFF_AH + tid * ROWB;
    } else {
        gp = (const char*)(g_Wh + woff + (size_t)(nbase + tid - 128) * DIM);
        so = OFF_BH + (tid - 128) * ROWB;
    }

    // ---- warp tiling: 8 warps as 4(m) x 2(n); warp tile 32x64
    const int wm = (w & 3) * 32;
    const int wn = (w >> 2) * 64;
    const int lr = lane & 15;
    const int lkb = (lane >> 4) * 16;

    float acc[2][8][4];
    #pragma unroll
    for (int mi = 0; mi < 2; ++mi)
        #pragma unroll
        for (int nj = 0; nj < 8; ++nj)
            #pragma unroll
            for (int q = 0; q < 4; ++q) acc[mi][nj][q] = 0.f;

    // prologue: stages 0, 1
    #pragma unroll
    for (int s = 0; s < 2; ++s) {
        const uint32_t d = sb + s * STGB + so;
        const char* g = gp + s * (BK * 2);
        #pragma unroll
        for (int q = 0; q < 8; ++q)
            CP_ASYNC16(d + q * 16, g + q * 16, sz);
        CP_COMMIT();
    }

    int rd = 0, wr = 2;
    for (int it = 0; it < KIT; ++it) {
        CP_WAIT_1();
        __syncthreads();

        if (it + 2 < KIT) {
            const uint32_t d = sb + wr * STGB + so;
            const char* g = gp + (it + 2) * (BK * 2);
            #pragma unroll
            for (int q = 0; q < 8; ++q)
                CP_ASYNC16(d + q * 16, g + q * 16, sz);
        }
        CP_COMMIT();

        const uint32_t sgb = sb + rd * STGB;
        #pragma unroll
        for (int kk = 0; kk < 4; ++kk) {       // four k16 steps in BK=64
            const uint32_t kb = kk * 32 + lkb;
            uint32_t ah[2][4];
            #pragma unroll
            for (int mi = 0; mi < 2; ++mi) {
                const uint32_t ro = (uint32_t)(wm + mi * 16 + lr) * ROWB + kb;
                LDM_X4(ah[mi], sgb + OFF_AH + ro);
            }
            #pragma unroll
            for (int njp = 0; njp < 4; ++njp) {
                uint32_t bh[4];
                const uint32_t ro = (uint32_t)(wn + njp * 16 + lr) * ROWB + kb;
                LDM_X4(bh, sgb + OFF_BH + ro);
                #pragma unroll
                for (int mi = 0; mi < 2; ++mi)
                    #pragma unroll
                    for (int t = 0; t < 2; ++t)
                        MMA(acc[mi][njp * 2 + t], ah[mi], bh[t], bh[t + 2]);
            }
        }
        rd = (rd == 2) ? 0 : rd + 1;
        wr = (wr == 2) ? 0 : wr + 1;
    }

    const int gid = lane >> 2;
    const int tq = lane & 3;

    if (MODE == 1) {
        #pragma unroll
        for (int mi = 0; mi < 2; ++mi) {
            #pragma unroll
            for (int rh = 0; rh < 2; ++rh) {
                const int mloc = wm + mi * 16 + gid + rh * 8;
                const int tok = stok[mloc];
                if (tok < 0) continue;
                const float pt = g_p[tok];
                float* dst = C + (size_t)tok * DIM;
                #pragma unroll
                for (int nj = 0; nj < 8; ++nj) {
                    const int n = nbase + wn + nj * 8 + tq * 2;
                    float v0 = fmaxf(acc[mi][nj][rh * 2]     + bias[n], 0.f) * pt;
                    float v1 = fmaxf(acc[mi][nj][rh * 2 + 1] + bias[n + 1], 0.f) * pt;
                    *(float2*)(dst + n) = make_float2(v0, v1);
                }
            }
        }
        return;
    }

    // ================= gating epilogue: partials =================
    {
        float* st_m1 = (float*)smem;          // 256 entries per array
        float* st_m2 = st_m1 + 256;
        float* st_s  = st_m1 + 512;
        int*   st_i1 = (int*)(st_m1 + 768);
        int*   st_i2 = (int*)(st_m1 + 1024);
        const int wnidx = w >> 2;             // 0..1
        __syncthreads();                      // pipeline reads of slot 0 done

        #pragma unroll
        for (int mi = 0; mi < 2; ++mi) {
            #pragma unroll
            for (int rh = 0; rh < 2; ++rh) {
                const int row = wm + mi * 16 + gid + rh * 8;
                float m1 = -3.4e38f, m2 = -3.4e38f;
                int i1 = 0x7fffffff, i2 = 0x7fffffff;
                float vals[16];
                #pragma unroll
                for (int nj = 0; nj < 8; ++nj) {
                    #pragma unroll
                    for (int cc = 0; cc < 2; ++cc) {
                        const int n = nbase + wn + nj * 8 + tq * 2 + cc;
                        const float v = acc[mi][nj][rh * 2 + cc] + bias[n];
                        vals[nj * 2 + cc] = v;
                        if (v > m1) { m2 = m1; i2 = i1; m1 = v; i1 = n; }
                        else if (v > m2) { m2 = v; i2 = n; }
                    }
                }
                float s = 0.f;
                #pragma unroll
                for (int q = 0; q < 16; ++q) s += expf(vals[q] - m1);
                #pragma unroll
                for (int off = 1; off <= 2; off <<= 1) {
                    const float om1 = __shfl_xor_sync(0xffffffffu, m1, off);
                    const int   oi1 = __shfl_xor_sync(0xffffffffu, i1, off);
                    const float om2 = __shfl_xor_sync(0xffffffffu, m2, off);
                    const int   oi2 = __shfl_xor_sync(0xffffffffu, i2, off);
                    const float os  = __shfl_xor_sync(0xffffffffu, s,  off);
                    merge5(m1, i1, m2, i2, s, om1, oi1, om2, oi2, os);
                }
                if (tq == 0) {
                    const int idx = wnidx * 128 + row;
                    st_m1[idx] = m1; st_m2[idx] = m2; st_s[idx] = s;
                    st_i1[idx] = i1; st_i2[idx] = i2;
                }
            }
        }
        __syncthreads();
        if (tid < 128) {
            float m1 = st_m1[tid], m2 = st_m2[tid], s = st_s[tid];
            int i1 = st_i1[tid], i2 = st_i2[tid];
            const int idx = 128 + tid;
            merge5(m1, i1, m2, i2, s,
                   st_m1[idx], st_i1[idx], st_m2[idx], st_i2[idx], st_s[idx]);
            float* P = g_part + (size_t)(mbase + tid) * 64 + blockIdx.x * 8;
            P[0] = m1; P[1] = m2; P[2] = s;
            P[3] = __int_as_float(i1); P[4] = __int_as_float(i2);
        }
    }

    // ================= fused route: last CTA of this row-block =============
    __shared__ int s_last;
    __syncthreads();
    if (tid == 0) {
        __threadfence();
        const int v = atomicAdd(&g_done[blockIdx.y], 1);
        s_last = (v == NTILE - 1);
    }
    __syncthreads();
    if (!s_last) return;

    __shared__ float r_m1[128], r_m2[128], r_sum[128];
    __shared__ int   r_i1[128], r_i2[128];
    __shared__ int   amb_list[128];
    __shared__ int   amb_cnt;
    if (tid == 0) amb_cnt = 0;
    __syncthreads();

    if (tid < 128) {
        const int t = mbase + tid;
        const float* P = g_part + (size_t)t * 64;
        float m1 = P[0], m2 = P[1], s = P[2];
        int i1 = __float_as_int(P[3]), i2 = __float_as_int(P[4]);
        #pragma unroll
        for (int x = 1; x < NTILE; ++x) {
            const float* Q = P + x * 8;
            merge5(m1, i1, m2, i2, s,
                   Q[0], __float_as_int(Q[3]), Q[1], __float_as_int(Q[4]), Q[2]);
        }
        r_m1[tid] = m1; r_m2[tid] = m2; r_sum[tid] = s;
        r_i1[tid] = i1; r_i2[tid] = i2;
        if ((m1 - m2) < GAP_THRESH) {
            const int p = atomicAdd(&amb_cnt, 1);
            amb_list[p] = tid;
        }
    }
    __syncthreads();

    for (int a = w; a < amb_cnt; a += 8) {
        const int li = amb_list[a];
        const int t = mbase + li;
        const int c1 = r_i1[li], c2 = r_i2[li];
        float p1 = 0.f, p2 = 0.f;
        const float* xr = X32 + (size_t)t * DIM;
        for (int k = lane; k < DIM; k += 32) {
            const float xv = xr[k];
            p1 += xv * Wg32[(size_t)k * DIM + c1];
            p2 += xv * Wg32[(size_t)k * DIM + c2];
        }
        #pragma unroll
        for (int off = 16; off > 0; off >>= 1) {
            p1 += __shfl_down_sync(0xffffffffu, p1, off);
            p2 += __shfl_down_sync(0xffffffffu, p2, off);
        }
        if (lane == 0) {
            const float d1 = bias[c1] + p1;
            const float d2 = bias[c2] + p2;
            if (d2 > d1 || (d2 == d1 && c2 < c1)) { r_i1[li] = c2; r_m1[li] = r_m2[li]; }
        }
    }
    __syncthreads();

    if (tid < 128) {
        const int t = mbase + tid;
        const int chosen = r_i1[tid];
        const int ex = chosen & (NEXP - 1);
        const int pos = atomicAdd(&g_cnt[ex], 1);
        g_tok[ex * NTOK + pos] = t;
        const float lmax = fmaxf(r_m1[tid], r_m2[tid]);
        g_p[t] = expf(r_m1[tid] - lmax) / r_sum[tid];
    }
}

// =====================================================================
extern "C" void kernel_launch(void* const* d_in, const int* in_sizes, int n_in,
                              void* d_out, int out_size) {
    const float* x  = (const float*)d_in[0];
    const float* Wg = (const float*)d_in[1];
    const float* bg = (const float*)d_in[2];
    const float* We = (const float*)d_in[3];
    const float* be = (const float*)d_in[4];
    float* out = (float*)d_out;

    cudaFuncSetAttribute(k_gemm<0>, cudaFuncAttributeMaxDynamicSharedMemorySize, SMEM_BYTES);
    cudaFuncSetAttribute(k_gemm<1>, cudaFuncAttributeMaxDynamicSharedMemorySize, SMEM_BYTES);

    k_prep<<<NBLK_WG + NBLK_X, 256>>>(x, Wg);
    k_gemm<0><<<dim3(NTILE, NROW + 16), 256, SMEM_BYTES>>>(bg, nullptr, x, Wg, We);
    k_gemm<1><<<dim3(NTILE, NROW, NEXP), 256, SMEM_BYTES>>>(be, out, nullptr, nullptr, nullptr);
}

// round 16
// speedup vs baseline: 2.0294x; 2.0294x over previous
#include <cuda_runtime.h>
#include <cuda_fp16.h>
#include <math.h>
#include <stdint.h>

#define DIM  1024
#define NEXP 8
#define NTOK 16384
#define BM   128
#define BN   256
#define BK   64
#define KIT  (DIM/BK)        // 16 stages
#define ROWB 144             // 64 halves (128B) + 16B pad
#define OFF_AH 0
#define OFF_BH (128*ROWB)               // 18432
#define STGB   (OFF_BH + 256*ROWB)      // 55296
#define NSTG 3
#define SMEM_BYTES (NSTG*STGB)          // 165888
#define GAP_THRESH 5.0e-3f
#define NROW (NTOK/BM)                  // 128 row-blocks

// ---------------- device-global scratch (allocation-free) ----------------
__device__ __half g_Xh[(size_t)NTOK * DIM];
__device__ __half g_Wh[(size_t)(1 + NEXP) * DIM * DIM];   // [N][K] fp16
__device__ float  g_part[(size_t)NTOK * 32];
__device__ int    g_cnt[NEXP];
__device__ int    g_done[NROW];
__device__ int    g_tok[NEXP * NTOK];
__device__ float  g_p[NTOK];

// ---------------- PTX helpers ----------------
static __device__ __forceinline__ uint32_t smem_u32(const void* p) {
    uint32_t a;
    asm("{ .reg .u64 t; cvta.to.shared.u64 t, %1; cvt.u32.u64 %0, t; }" : "=r"(a) : "l"(p));
    return a;
}
#define CP_ASYNC16(dst, src, sz) \
    asm volatile("cp.async.cg.shared.global [%0], [%1], 16, %2;" \
                 :: "r"(dst), "l"(src), "r"(sz) : "memory")
#define CP_COMMIT() asm volatile("cp.async.commit_group;" ::: "memory")
#define CP_WAIT_1() asm volatile("cp.async.wait_group 1;" ::: "memory")

#define LDM_X4(r, addr) \
    asm volatile("ldmatrix.sync.aligned.m8n8.x4.shared.b16 {%0,%1,%2,%3}, [%4];" \
                 : "=r"((r)[0]), "=r"((r)[1]), "=r"((r)[2]), "=r"((r)[3]) : "r"(addr))

#define MMA(d, a, b0_, b1_) \
    asm volatile("mma.sync.aligned.m16n8k16.row.col.f32.f16.f16.f32 " \
                 "{%0,%1,%2,%3},{%4,%5,%6,%7},{%8,%9},{%0,%1,%2,%3};" \
                 : "+f"((d)[0]), "+f"((d)[1]), "+f"((d)[2]), "+f"((d)[3]) \
                 : "r"((a)[0]), "r"((a)[1]), "r"((a)[2]), "r"((a)[3]), \
                   "r"(b0_), "r"(b1_))

// ---- top-2 merge (first-index tie-break, jnp.argmax compatible) ----
static __device__ __forceinline__ void merge_top2(float& m1, int& i1, float& m2, int& i2,
                                                  float om1, int oi1, float om2, int oi2) {
    if (om1 > m1 || (om1 == m1 && oi1 < i1)) {
        float c = m1; int ci = i1;
        m1 = om1; i1 = oi1;
        if (om2 > c || (om2 == c && oi2 < ci)) { m2 = om2; i2 = oi2; }
        else                                   { m2 = c;   i2 = ci;  }
    } else {
        if (om1 > m2 || (om1 == m2 && oi1 < i2)) { m2 = om1; i2 = oi1; }
    }
}
static __device__ __forceinline__ void merge5(float& m1, int& i1, float& m2, int& i2, float& s,
                                              float om1, int oi1, float om2, int oi2, float os) {
    const float M = fmaxf(m1, om1);
    s = s * expf(m1 - M) + os * expf(om1 - M);
    merge_top2(m1, i1, m2, i2, om1, oi1, om2, oi2);
}

// =====================================================================
// Prep: blocks [0,1024) transpose Wg -> g_Wh[z=0]; blocks [1024, 17408)
// convert x -> g_Xh. Block 0 also resets counters. 256 threads.
// =====================================================================
#define NBLK_WG 1024
#define NBLK_X  (NTOK * DIM / 4 / 256)   // 16384
__global__ __launch_bounds__(256) void k_prep(const float* __restrict__ X,
                                              const float* __restrict__ Wg) {
    const int id = blockIdx.x;
    const int tid = threadIdx.x;
    if (id == 0) {
        if (tid < NEXP) g_cnt[tid] = 0;
        if (tid < NROW) g_done[tid] = 0;
    }

    if (id < NBLK_WG) {
        __shared__ float t[32][33];
        const int bx = id & 31, by = id >> 5;
        const int tx = tid & 31, ty = tid >> 5;
        #pragma unroll
        for (int i = 0; i < 32; i += 8)
            t[ty + i][tx] = Wg[(size_t)(by * 32 + ty + i) * DIM + bx * 32 + tx];
        __syncthreads();
        #pragma unroll
        for (int i = 0; i < 32; i += 8)
            g_Wh[(size_t)(bx * 32 + ty + i) * DIM + by * 32 + tx] =
                __float2half_rn(t[tx][ty + i]);
    } else {
        const size_t i = (size_t)(id - NBLK_WG) * 256 + tid;
        float4 v = ((const float4*)X)[i];
        ((__half2*)g_Xh)[2 * i]     = __halves2half2(__float2half_rn(v.x), __float2half_rn(v.y));
        ((__half2*)g_Xh)[2 * i + 1] = __halves2half2(__float2half_rn(v.z), __float2half_rn(v.w));
    }
}

// =====================================================================
// fp16 GEMM via mma.sync (fp32 acc), BK=64, 3-stage cp.async pipeline.
// 512 threads = 16 warps as 4(m) x 4(n); warp tile 32x64; block 128x256.
// MODE 0: gating; grid (4, 128+32):
//   y <  128 : GEMM tile -> partials; last CTA of each row merges, rescues,
//              and appends routing (fused k_route).
//   y >= 128 : We transpose CTAs (fill tail wave).
// MODE 1: expert -> out = relu(x@We[e] + be[e]) * p   (rows gathered)
// =====================================================================
template <int MODE>
__global__ __launch_bounds__(512, 1) void k_gemm(const float* __restrict__ bias_,
                                                 float* __restrict__ C,
                                                 const float* __restrict__ X32,
                                                 const float* __restrict__ Wg32,
                                                 const float* __restrict__ We32) {
    extern __shared__ char smem[];
    __shared__ int stok[BM];

    const int tid = threadIdx.x;
    const int lane = tid & 31;
    const int w = tid >> 5;

    // ================= We transpose CTAs (MODE 0, y >= 128) ================
    if (MODE == 0 && blockIdx.y >= NROW) {
        const int c_ = (blockIdx.y - NROW) * 4 + blockIdx.x;   // 0..127
        const int e = c_ >> 4;
        const int c0 = (c_ & 15) * 64;
        const float* src = We32 + (size_t)e * DIM * DIM;       // [K][N]
        __half* dst = g_Wh + (size_t)(1 + e) * DIM * DIM;      // [N][K]
        float* sbuf = (float*)smem;             // [64][65]
        const int rowt = tid >> 3;
        const int colt = (tid & 7) * 8;
        for (int r0 = 0; r0 < DIM; r0 += 64) {
            float4 v0 = *(const float4*)&src[(size_t)(r0 + rowt) * DIM + c0 + colt];
            float4 v1 = *(const float4*)&src[(size_t)(r0 + rowt) * DIM + c0 + colt + 4];
            __syncthreads();
            float* dr = &sbuf[rowt * 65 + colt];
            dr[0] = v0.x; dr[1] = v0.y; dr[2] = v0.z; dr[3] = v0.w;
            dr[4] = v1.x; dr[5] = v1.y; dr[6] = v1.z; dr[7] = v1.w;
            __syncthreads();
            __half tmp[8];
            #pragma unroll
            for (int j = 0; j < 8; ++j)
                tmp[j] = __float2half_rn(sbuf[(colt + j) * 65 + rowt]);
            *(uint4*)&dst[(size_t)(c0 + rowt) * DIM + r0 + colt] = *(uint4*)tmp;
        }
        return;
    }

    const int mbase = blockIdx.y * BM;
    const int nbase = blockIdx.x * BN;

    const float* bias = bias_;
    size_t woff = 0;
    if (MODE == 1) {
        const int e = blockIdx.z;
        const int cnt = g_cnt[e];
        if (mbase >= cnt) return;
        woff = (size_t)(1 + e) * DIM * DIM;
        bias = bias_ + e * DIM;
        if (tid < BM) {
            const int i = mbase + tid;
            stok[tid] = (i < cnt) ? g_tok[e * NTOK + i] : -1;
        }
    } else {
        if (tid < BM) stok[tid] = mbase + tid;
    }
    __syncthreads();

    const uint32_t sb = smem_u32(smem);

    const int c8 = (tid & 7) * 16;
    const int r0_ = tid >> 3;
    const int tokA0 = stok[r0_];
    const int tokA1 = stok[r0_ + 64];
    const char* gA0 = (const char*)(g_Xh + (size_t)(tokA0 >= 0 ? tokA0 : 0) * DIM) + c8;
    const char* gA1 = (const char*)(g_Xh + (size_t)(tokA1 >= 0 ? tokA1 : 0) * DIM) + c8;
    const uint32_t szA0 = (tokA0 >= 0) ? 16u : 0u;
    const uint32_t szA1 = (tokA1 >= 0) ? 16u : 0u;
    const uint32_t soA0 = OFF_AH + r0_ * ROWB + c8;
    const uint32_t soA1 = soA0 + 64 * ROWB;
    const char* gB = (const char*)(g_Wh + woff + (size_t)(nbase + r0_) * DIM) + c8;
    const uint32_t soB = OFF_BH + r0_ * ROWB + c8;

    const int wm = (w & 3) * 32;
    const int wn = (w >> 2) * 64;
    const int lr = lane & 15;
    const int lkb = (lane >> 4) * 16;

    float acc[2][8][4];
    #pragma unroll
    for (int mi = 0; mi < 2; ++mi)
        #pragma unroll
        for (int nj = 0; nj < 8; ++nj)
            #pragma unroll
            for (int q = 0; q < 4; ++q) acc[mi][nj][q] = 0.f;

    #pragma unroll
    for (int s = 0; s < 2; ++s) {
        const uint32_t d = sb + s * STGB;
        const int ko = s * (BK * 2);
        CP_ASYNC16(d + soA0, gA0 + ko, szA0);
        CP_ASYNC16(d + soA1, gA1 + ko, szA1);
        #pragma unroll
        for (int tb = 0; tb < 4; ++tb)
            CP_ASYNC16(d + soB + tb * (64 * ROWB), gB + tb * (64 * DIM * 2) + ko, 16u);
        CP_COMMIT();
    }

    int rd = 0, wr = 2;
    for (int it = 0; it < KIT; ++it) {
        CP_WAIT_1();
        __syncthreads();

        if (it + 2 < KIT) {
            const uint32_t d = sb + wr * STGB;
            const int ko = (it + 2) * (BK * 2);
            CP_ASYNC16(d + soA0, gA0 + ko, szA0);
            CP_ASYNC16(d + soA1, gA1 + ko, szA1);
            #pragma unroll
            for (int tb = 0; tb < 4; ++tb)
                CP_ASYNC16(d + soB + tb * (64 * ROWB), gB + tb * (64 * DIM * 2) + ko, 16u);
        }
        CP_COMMIT();

        const uint32_t sgb = sb + rd * STGB;
        #pragma unroll
        for (int kk = 0; kk < 4; ++kk) {
            const uint32_t kb = kk * 32 + lkb;
            uint32_t ah[2][4];
            #pragma unroll
            for (int mi = 0; mi < 2; ++mi) {
                const uint32_t ro = (uint32_t)(wm + mi * 16 + lr) * ROWB + kb;
                LDM_X4(ah[mi], sgb + OFF_AH + ro);
            }
            #pragma unroll
            for (int njp = 0; njp < 4; ++njp) {
                uint32_t bh[4];
                const uint32_t ro = (uint32_t)(wn + njp * 16 + lr) * ROWB + kb;
                LDM_X4(bh, sgb + OFF_BH + ro);
                #pragma unroll
                for (int mi = 0; mi < 2; ++mi)
                    #pragma unroll
                    for (int t = 0; t < 2; ++t)
                        MMA(acc[mi][njp * 2 + t], ah[mi], bh[t], bh[t + 2]);
            }
        }
        rd = (rd == 2) ? 0 : rd + 1;
        wr = (wr == 2) ? 0 : wr + 1;
    }

    const int gid = lane >> 2;
    const int tq = lane & 3;

    if (MODE == 1) {
        #pragma unroll
        for (int mi = 0; mi < 2; ++mi) {
            #pragma unroll
            for (int rh = 0; rh < 2; ++rh) {
                const int mloc = wm + mi * 16 + gid + rh * 8;
                const int tok = stok[mloc];
                if (tok < 0) continue;
                const float pt = g_p[tok];
                float* dst = C + (size_t)tok * DIM;
                #pragma unroll
                for (int nj = 0; nj < 8; ++nj) {
                    const int n = nbase + wn + nj * 8 + tq * 2;
                    float v0 = fmaxf(acc[mi][nj][rh * 2]     + bias[n], 0.f) * pt;
                    float v1 = fmaxf(acc[mi][nj][rh * 2 + 1] + bias[n + 1], 0.f) * pt;
                    *(float2*)(dst + n) = make_float2(v0, v1);
                }
            }
        }
        return;
    }

    // ================= gating epilogue: partials =================
    {
        float* st_m1 = (float*)(smem + STGB);
        float* st_m2 = st_m1 + 512;
        float* st_s  = st_m1 + 1024;
        int*   st_i1 = (int*)(st_m1 + 1536);
        int*   st_i2 = (int*)(st_m1 + 2048);
        const int wnidx = w >> 2;

        #pragma unroll
        for (int mi = 0; mi < 2; ++mi) {
            #pragma unroll
            for (int rh = 0; rh < 2; ++rh) {
                const int row = wm + mi * 16 + gid + rh * 8;
                float m1 = -3.4e38f, m2 = -3.4e38f;
                int i1 = 0x7fffffff, i2 = 0x7fffffff;
                float vals[16];
                #pragma unroll
                for (int nj = 0; nj < 8; ++nj) {
                    #pragma unroll
                    for (int cc = 0; cc < 2; ++cc) {
                        const int n = nbase + wn + nj * 8 + tq * 2 + cc;
                        const float v = acc[mi][nj][rh * 2 + cc] + bias[n];
                        vals[nj * 2 + cc] = v;
                        if (v > m1) { m2 = m1; i2 = i1; m1 = v; i1 = n; }
                        else if (v > m2) { m2 = v; i2 = n; }
                    }
                }
                float s = 0.f;
                #pragma unroll
                for (int q = 0; q < 16; ++q) s += expf(vals[q] - m1);
                #pragma unroll
                for (int off = 1; off <= 2; off <<= 1) {
                    const float om1 = __shfl_xor_sync(0xffffffffu, m1, off);
                    const int   oi1 = __shfl_xor_sync(0xffffffffu, i1, off);
                    const float om2 = __shfl_xor_sync(0xffffffffu, m2, off);
                    const int   oi2 = __shfl_xor_sync(0xffffffffu, i2, off);
                    const float os  = __shfl_xor_sync(0xffffffffu, s,  off);
                    merge5(m1, i1, m2, i2, s, om1, oi1, om2, oi2, os);
                }
                if (tq == 0) {
                    const int idx = wnidx * 128 + row;
                    st_m1[idx] = m1; st_m2[idx] = m2; st_s[idx] = s;
                    st_i1[idx] = i1; st_i2[idx] = i2;
                }
            }
        }
        __syncthreads();
        if (tid < 128) {
            float m1 = st_m1[tid], m2 = st_m2[tid], s = st_s[tid];
            int i1 = st_i1[tid], i2 = st_i2[tid];
            #pragma unroll
            for (int x = 1; x < 4; ++x) {
                const int idx = x * 128 + tid;
                merge5(m1, i1, m2, i2, s,
                       st_m1[idx], st_i1[idx], st_m2[idx], st_i2[idx], st_s[idx]);
            }
            float* P = g_part + (size_t)(mbase + tid) * 32 + blockIdx.x * 8;
            P[0] = m1; P[1] = m2; P[2] = s;
            P[3] = __int_as_float(i1); P[4] = __int_as_float(i2);
        }
    }

    // ================= fused route: last CTA of this row-block =============
    __shared__ int s_last;
    __syncthreads();
    if (tid == 0) {
        __threadfence();
        const int v = atomicAdd(&g_done[blockIdx.y], 1);
        s_last = (v == 3);
    }
    __syncthreads();
    if (!s_last) return;

    __shared__ float r_m1[128], r_m2[128], r_sum[128];
    __shared__ int   r_i1[128], r_i2[128];
    __shared__ int   amb_list[128];
    __shared__ int   amb_cnt;
    if (tid == 0) amb_cnt = 0;
    __syncthreads();

    if (tid < 128) {
        const int t = mbase + tid;
        const float* P = g_part + (size_t)t * 32;
        float m1 = P[0], m2 = P[1], s = P[2];
        int i1 = __float_as_int(P[3]), i2 = __float_as_int(P[4]);
        #pragma unroll
        for (int x = 1; x < 4; ++x) {
            const float* Q = P + x * 8;
            merge5(m1, i1, m2, i2, s,
                   Q[0], __float_as_int(Q[3]), Q[1], __float_as_int(Q[4]), Q[2]);
        }
        r_m1[tid] = m1; r_m2[tid] = m2; r_sum[tid] = s;
        r_i1[tid] = i1; r_i2[tid] = i2;
        if ((m1 - m2) < GAP_THRESH) {
            const int p = atomicAdd(&amb_cnt, 1);
            amb_list[p] = tid;
        }
    }
    __syncthreads();

    for (int a = w; a < amb_cnt; a += 16) {
        const int li = amb_list[a];
        const int t = mbase + li;
        const int c1 = r_i1[li], c2 = r_i2[li];
        float p1 = 0.f, p2 = 0.f;
        const float* xr = X32 + (size_t)t * DIM;
        for (int k = lane; k < DIM; k += 32) {
            const float xv = xr[k];
            p1 += xv * Wg32[(size_t)k * DIM + c1];
            p2 += xv * Wg32[(size_t)k * DIM + c2];
        }
        #pragma unroll
        for (int off = 16; off > 0; off >>= 1) {
            p1 += __shfl_down_sync(0xffffffffu, p1, off);
            p2 += __shfl_down_sync(0xffffffffu, p2, off);
        }
        if (lane == 0) {
            const float d1 = bias[c1] + p1;
            const float d2 = bias[c2] + p2;
            if (d2 > d1 || (d2 == d1 && c2 < c1)) { r_i1[li] = c2; r_m1[li] = r_m2[li]; }
        }
    }
    __syncthreads();

    if (tid < 128) {
        const int t = mbase + tid;
        const int chosen = r_i1[tid];
        const int ex = chosen & (NEXP - 1);
        const int pos = atomicAdd(&g_cnt[ex], 1);
        g_tok[ex * NTOK + pos] = t;
        const float lmax = fmaxf(r_m1[tid], r_m2[tid]);
        g_p[t] = expf(r_m1[tid] - lmax) / r_sum[tid];
    }
}

// =====================================================================
extern "C" void kernel_launch(void* const* d_in, const int* in_sizes, int n_in,
                              void* d_out, int out_size) {
    const float* x  = (const float*)d_in[0];
    const float* Wg = (const float*)d_in[1];
    const float* bg = (const float*)d_in[2];
    const float* We = (const float*)d_in[3];
    const float* be = (const float*)d_in[4];
    float* out = (float*)d_out;

    cudaFuncSetAttribute(k_gemm<0>, cudaFuncAttributeMaxDynamicSharedMemorySize, SMEM_BYTES);
    cudaFuncSetAttribute(k_gemm<1>, cudaFuncAttributeMaxDynamicSharedMemorySize, SMEM_BYTES);

    k_prep<<<NBLK_WG + NBLK_X, 256>>>(x, Wg);
    k_gemm<0><<<dim3(DIM / BN, NROW + 32), 512, SMEM_BYTES>>>(bg, nullptr, x, Wg, We);
    k_gemm<1><<<dim3(DIM / BN, NROW, NEXP), 512, SMEM_BYTES>>>(be, out, nullptr, nullptr, nullptr);
}